// round 5
// baseline (speedup 1.0000x reference)
#include <cuda_runtime.h>
#include <math.h>

// Fixed problem shapes
#define BH 32            // B*H
#define LL 2048
#define DD 64
#define UU 40            // top-k count
#define SK 40            // sample_k
#define NS 64            // key-chunks for split softmax (warp-sized chunks)
#define CK 32            // keys per chunk (NS*CK == LL)
#define NCH 4            // K chunks for m staging
#define CROWS 512        // rows per staged chunk
#define QPB 512          // queries per m-kernel block

// Scratch (device globals; no allocation allowed)
__device__ float g_M[BH * LL];
__device__ int   g_top[BH * UU];
__device__ float g_pm[BH * UU * NS];
__device__ float g_pl[BH * UU * NS];
__device__ float g_pacc[BH * UU * NS * DD];   // 21 MB
__device__ int   g_sidx[LL * SK];             // samples reordered by chunk (local row)
__device__ int   g_soff[LL * (NCH + 1)];      // per-q chunk offsets

// ---------------------------------------------------------------------------
// Kernel 0: bucket each query's samples by 512-row chunk (idx shared over bh).
// grid = LL/256, block = 256, thread per query.
// ---------------------------------------------------------------------------
__global__ void sort_samples_kernel(const int* __restrict__ idxs) {
    const int q = blockIdx.x * 256 + threadIdx.x;
    int v[SK];
    int cnt[NCH] = {0, 0, 0, 0};
#pragma unroll
    for (int s = 0; s < SK; s++) {
        v[s] = __ldg(idxs + q * SK + s);
        cnt[v[s] >> 9]++;
    }
    int off[NCH + 1];
    off[0] = 0;
#pragma unroll
    for (int c = 0; c < NCH; c++) off[c + 1] = off[c] + cnt[c];
    int w[NCH];
#pragma unroll
    for (int c = 0; c < NCH; c++) w[c] = off[c];
#pragma unroll
    for (int s = 0; s < SK; s++) {
        const int c = v[s] >> 9;
        g_sidx[q * SK + (w[c]++)] = v[s] & (CROWS - 1);   // local row in chunk
    }
#pragma unroll
    for (int c = 0; c <= NCH; c++) g_soff[q * (NCH + 1) + c] = off[c];
}

// ---------------------------------------------------------------------------
// Kernel 1: cumsum of values along L, written to d_out.
// grid = BH*4 (16-dim groups), block = 1024.
// ---------------------------------------------------------------------------
__global__ void cumsum_kernel(const float* __restrict__ V, float* __restrict__ out) {
    const int bh    = blockIdx.x >> 2;
    const int dg    = blockIdx.x & 3;
    const int dl    = threadIdx.x & 15;
    const int d     = dg * 16 + dl;
    const int chunk = threadIdx.x >> 4;     // 0..63
    const int RPC   = 32;
    const size_t base = (size_t)bh * LL * DD;
    const float* vp = V + base + (size_t)chunk * RPC * DD + d;

    float s = 0.f;
#pragma unroll 8
    for (int i = 0; i < RPC; i++) s += vp[(size_t)i * DD];

    __shared__ float cs[64 * 16];
    cs[chunk * 16 + dl] = s;
    __syncthreads();

    float off = 0.f;
    for (int c = 0; c < chunk; c++) off += cs[c * 16 + dl];

    float* op = out + base + (size_t)chunk * RPC * DD + d;
    float acc = off;
#pragma unroll 8
    for (int i = 0; i < RPC; i++) {
        acc += vp[(size_t)i * DD];
        op[(size_t)i * DD] = acc;
    }
}

// ---------------------------------------------------------------------------
// Kernel 2: M[bh,q] = max_s(QK_s) - sum_s(QK_s)/L. smem-staged, 4 samples per
// warp iteration in 8-lane groups, indices preloaded to regs.
// grid = BH*4 = 128, block = 1024 (32 warps; warp handles 16 queries).
// dynamic smem: CROWS*DD floats (128 KB).
// ---------------------------------------------------------------------------
__global__ void __launch_bounds__(1024) m3_kernel(const float* __restrict__ Q,
                                                  const float* __restrict__ K) {
    extern __shared__ float Kc[];                 // [CROWS][DD]
    __shared__ float mS[QPB];
    __shared__ float sS[QPB];

    const int bh = blockIdx.x >> 2;
    const int qb = blockIdx.x & 3;
    const int q0 = qb * QPB;
    const size_t base = (size_t)bh * LL * DD;
    const int tid   = threadIdx.x;
    const int warp  = tid >> 5;
    const int lane  = tid & 31;
    const int g     = lane & 7;                   // dim-group within sample
    const int s_sub = lane >> 3;                  // which of 4 samples

    for (int i = tid; i < QPB; i += 1024) { mS[i] = -INFINITY; sS[i] = 0.f; }

    for (int c = 0; c < NCH; c++) {
        __syncthreads();
        // stage chunk c of K: CROWS*DD floats = 8192 float4 across 1024 threads
        const float4* src = (const float4*)(K + base + (size_t)c * CROWS * DD);
        float4* dst = (float4*)Kc;
#pragma unroll
        for (int i = 0; i < (CROWS * DD / 4) / 1024; i++)      // 8 iters
            dst[i * 1024 + tid] = __ldg(src + i * 1024 + tid);
        __syncthreads();

        for (int qi = 0; qi < 16; qi++) {
            const int ql = warp * 16 + qi;        // local query id
            const int q  = q0 + ql;
            const int jb = __ldg(&g_soff[q * (NCH + 1) + c]);
            const int je = __ldg(&g_soff[q * (NCH + 1) + c + 1]);
            const int cnt = je - jb;
            if (cnt <= 0) continue;

            // Q dims [4g,4g+4) and [32+4g, 32+4g+4)
            const float4 qa  = __ldg((const float4*)(Q + base + (size_t)q * DD) + g);
            const float4 qb4 = __ldg((const float4*)(Q + base + (size_t)q * DD) + 8 + g);

            // preload this query's chunk-local sample rows into 2 regs
            int r1 = 0, r2 = 0;
            if (jb + lane < SK)       r1 = __ldg(&g_sidx[q * SK + jb + lane]);
            if (jb + 32 + lane < SK)  r2 = __ldg(&g_sidx[q * SK + jb + 32 + lane]);

            float lm = -INFINITY, ls = 0.f;
            for (int bb = 0; bb < cnt; bb += 4) {
                const int sel   = bb + s_sub;
                const int a     = __shfl_sync(0xffffffffu, r1, sel & 31);
                const int b     = __shfl_sync(0xffffffffu, r2, sel & 31);
                const int r     = (sel < 32) ? a : b;
                const bool valid = sel < cnt;
                const int rr = valid ? r : 0;
                const float4 ka = *(const float4*)(Kc + rr * DD + g * 4);
                const float4 kb = *(const float4*)(Kc + rr * DD + 32 + g * 4);
                float d = qa.x * ka.x + qa.y * ka.y + qa.z * ka.z + qa.w * ka.w
                        + qb4.x * kb.x + qb4.y * kb.y + qb4.z * kb.z + qb4.w * kb.w;
                // reduce within 8-lane group (same sample)
                d += __shfl_xor_sync(0xffffffffu, d, 1);
                d += __shfl_xor_sync(0xffffffffu, d, 2);
                d += __shfl_xor_sync(0xffffffffu, d, 4);
                if (valid) { lm = fmaxf(lm, d); ls += d; }
            }
            // combine 4 sample-groups (invalid groups hold lm=-inf, ls=0)
            lm = fmaxf(lm, __shfl_xor_sync(0xffffffffu, lm, 8));
            ls += __shfl_xor_sync(0xffffffffu, ls, 8);
            lm = fmaxf(lm, __shfl_xor_sync(0xffffffffu, lm, 16));
            ls += __shfl_xor_sync(0xffffffffu, ls, 16);
            if (lane == 0) {
                mS[ql] = fmaxf(mS[ql], lm);
                sS[ql] += ls;
            }
        }
    }
    __syncthreads();
    for (int i = tid; i < QPB; i += 1024)
        g_M[bh * LL + q0 + i] = mS[i] - sS[i] * (1.0f / (float)LL);
}

// ---------------------------------------------------------------------------
// Kernel 3: top-40 of M per (b,h). grid = BH, block = 256 (8 warps).
// ---------------------------------------------------------------------------
__global__ void topk_kernel() {
    const int bh   = blockIdx.x;
    const int t    = threadIdx.x;
    const int warp = t >> 5;
    const int lane = t & 31;

    __shared__ float cv[8][UU];
    __shared__ int   ci[8][UU];

    const int ebase = warp * 256 + lane * 8;
    float v[8];
#pragma unroll
    for (int j = 0; j < 8; j++) v[j] = g_M[bh * LL + ebase + j];

    for (int it = 0; it < UU; it++) {
        float bv = -INFINITY; int bj = 0;
#pragma unroll
        for (int j = 0; j < 8; j++)
            if (v[j] > bv) { bv = v[j]; bj = j; }
        int bidx = ebase + bj;
#pragma unroll
        for (int off = 16; off; off >>= 1) {
            float ov = __shfl_xor_sync(0xffffffffu, bv, off);
            int   oi = __shfl_xor_sync(0xffffffffu, bidx, off);
            if (ov > bv || (ov == bv && oi < bidx)) { bv = ov; bidx = oi; }
        }
        if (bidx >= ebase && bidx < ebase + 8) v[bidx - ebase] = -INFINITY;
        if (lane == 0) { cv[warp][it] = bv; ci[warp][it] = bidx; }
    }
    __syncthreads();

    if (warp == 0) {
        int p = 0;
        for (int it = 0; it < UU; it++) {
            float hv = (lane < 8) ? cv[lane][p] : -INFINITY;
            int   hi = (lane < 8) ? ci[lane][p] : 0x7fffffff;
            float wv = hv; int wi = hi;
#pragma unroll
            for (int off = 4; off; off >>= 1) {
                float ov = __shfl_xor_sync(0xffffffffu, wv, off);
                int   oi = __shfl_xor_sync(0xffffffffu, wi, off);
                if (ov > wv || (ov == wv && oi < wi)) { wv = ov; wi = oi; }
            }
            wv = __shfl_sync(0xffffffffu, wv, 0);
            wi = __shfl_sync(0xffffffffu, wi, 0);
            if (lane < 8 && hi == wi) p++;
            if (lane == 0) g_top[bh * UU + it] = wi;
        }
    }
}

// ---------------------------------------------------------------------------
// Kernel 4: split-K attention partials, warp-autonomous 32-key chunks.
// grid = BH*16, block = 128 (4 warps; warp = one chunk of 32 keys).
// Lane=key for scores (K row in regs), lane=dim for PV (V cols in regs).
// No __syncthreads in the main loop.
// ---------------------------------------------------------------------------
__global__ void __launch_bounds__(128) attn_partial_kernel(const float* __restrict__ Q,
                                                           const float* __restrict__ K,
                                                           const float* __restrict__ V) {
    const int bh   = blockIdx.x >> 4;
    const int cgr  = blockIdx.x & 15;
    const int t    = threadIdx.x;
    const int warp = t >> 5;
    const int lane = t & 31;
    const int c    = cgr * 4 + warp;     // chunk 0..63
    const size_t base = (size_t)bh * LL * DD;
    const int k0 = c * CK;

    __shared__ int   topS[UU];
    __shared__ float Qs[UU][DD];

    if (t < UU) topS[t] = g_top[bh * UU + t];
    __syncthreads();
    for (int i = t; i < UU * 16; i += 128) {
        const int u = i >> 4, j = i & 15;
        *(float4*)&Qs[u][j * 4] = __ldg((const float4*)(Q + base + (size_t)topS[u] * DD) + j);
    }

    // K row of key (k0+lane) -> 64 regs
    float4 kreg[16];
    const float4* kp = (const float4*)(K + base + (size_t)(k0 + lane) * DD);
#pragma unroll
    for (int j = 0; j < 16; j++) kreg[j] = __ldg(kp + j);

    // V columns: lane owns dims (lane) and (lane+32) over 32 keys -> 64 regs
    float v0[CK], v1[CK];
#pragma unroll
    for (int k = 0; k < CK; k++) {
        v0[k] = __ldg(V + base + (size_t)(k0 + k) * DD + lane);
        v1[k] = __ldg(V + base + (size_t)(k0 + k) * DD + 32 + lane);
    }
    __syncthreads();   // Qs ready

    for (int u = 0; u < UU; u++) {
        const int pos = topS[u];
        const int pi  = (bh * UU + u) * NS + c;
        if (k0 > pos) {   // fully masked chunk (warp-uniform)
            if (lane == 0) { g_pm[pi] = -INFINITY; g_pl[pi] = 0.f; }
            continue;
        }
        // score for key k0+lane (Qs reads are warp-broadcast)
        float a0 = 0.f, a1 = 0.f, a2 = 0.f, a3 = 0.f;
#pragma unroll
        for (int j = 0; j < 16; j++) {
            const float4 kv = kreg[j];
            const float4 qv = *(const float4*)&Qs[u][j * 4];
            a0 += kv.x * qv.x; a1 += kv.y * qv.y;
            a2 += kv.z * qv.z; a3 += kv.w * qv.w;
        }
        float s = ((a0 + a1) + (a2 + a3)) * 0.125f;   // 1/sqrt(64)
        const int kg = k0 + lane;
        if (kg > pos) s = -INFINITY;

        float m = s;
#pragma unroll
        for (int off = 16; off; off >>= 1) m = fmaxf(m, __shfl_xor_sync(0xffffffffu, m, off));

        const float p = (kg <= pos) ? __expf(s - m) : 0.f;
        float l = p;
#pragma unroll
        for (int off = 16; off; off >>= 1) l += __shfl_xor_sync(0xffffffffu, l, off);

        // PV: lane = dim; broadcast p_k via shfl
        float acc0 = 0.f, acc1 = 0.f;
#pragma unroll
        for (int k = 0; k < CK; k++) {
            const float pk = __shfl_sync(0xffffffffu, p, k);
            acc0 += pk * v0[k];
            acc1 += pk * v1[k];
        }
        g_pacc[(size_t)pi * DD + lane]      = acc0;
        g_pacc[(size_t)pi * DD + 32 + lane] = acc1;
        if (lane == 0) { g_pm[pi] = m; g_pl[pi] = l; }
    }
}

// ---------------------------------------------------------------------------
// Kernel 5: combine partials (log-sum-exp) and scatter into d_out.
// grid = BH*UU, block = 64 (thread = dim).
// ---------------------------------------------------------------------------
__global__ void combine_kernel(float* __restrict__ out) {
    const int bhu = blockIdx.x;
    const int t   = threadIdx.x;
    const int bh  = bhu / UU;
    const int pos = g_top[bhu];

    float mx = -INFINITY;
#pragma unroll
    for (int c = 0; c < NS; c++) mx = fmaxf(mx, g_pm[bhu * NS + c]);

    float Ls = 0.f, acc = 0.f;
#pragma unroll 8
    for (int c = 0; c < NS; c++) {
        const float plv = g_pl[bhu * NS + c];
        if (plv > 0.f) {
            const float w = __expf(g_pm[bhu * NS + c] - mx);
            Ls  += plv * w;
            acc += w * g_pacc[(size_t)(bhu * NS + c) * DD + t];
        }
    }
    out[(size_t)bh * LL * DD + (size_t)pos * DD + t] = acc / Ls;
}

// ---------------------------------------------------------------------------
extern "C" void kernel_launch(void* const* d_in, const int* in_sizes, int n_in,
                              void* d_out, int out_size) {
    const float* Q   = (const float*)d_in[0];
    const float* K   = (const float*)d_in[1];
    const float* V   = (const float*)d_in[2];
    const int*   idx = (const int*)d_in[3];
    float* out = (float*)d_out;

    const int m3_smem = CROWS * DD * sizeof(float);   // 128 KB dynamic
    cudaFuncSetAttribute(m3_kernel, cudaFuncAttributeMaxDynamicSharedMemorySize, m3_smem);

    sort_samples_kernel<<<LL / 256, 256>>>(idx);
    cumsum_kernel<<<BH * 4, 1024>>>(V, out);
    m3_kernel<<<BH * 4, 1024, m3_smem>>>(Q, K);
    topk_kernel<<<BH, 256>>>();
    attn_partial_kernel<<<BH * 16, 128>>>(Q, K, V);
    combine_kernel<<<BH * UU, DD>>>(out);
}

// round 6
// speedup vs baseline: 1.0955x; 1.0955x over previous
#include <cuda_runtime.h>
#include <math.h>

// Fixed problem shapes
#define BH 32            // B*H
#define LL 2048
#define DD 64
#define UU 40            // top-k count
#define SK 40            // sample_k
#define NS 64            // key-chunks for split softmax (warp-sized chunks)
#define CK 32            // keys per chunk (NS*CK == LL)

// Scratch (device globals; no allocation allowed)
__device__ float g_M[BH * LL];
__device__ int   g_top[BH * UU];
__device__ float g_pm[BH * UU * NS];
__device__ float g_pl[BH * UU * NS];
__device__ float g_pacc[BH * UU * NS * DD];   // 21 MB

// ---------------------------------------------------------------------------
// Kernel 1: cumsum of values along L, written to d_out.
// grid = BH*4 (16-dim groups), block = 1024.
// ---------------------------------------------------------------------------
__global__ void cumsum_kernel(const float* __restrict__ V, float* __restrict__ out) {
    const int bh    = blockIdx.x >> 2;
    const int dg    = blockIdx.x & 3;
    const int dl    = threadIdx.x & 15;
    const int d     = dg * 16 + dl;
    const int chunk = threadIdx.x >> 4;     // 0..63
    const int RPC   = 32;
    const size_t base = (size_t)bh * LL * DD;
    const float* vp = V + base + (size_t)chunk * RPC * DD + d;

    float s = 0.f;
#pragma unroll 8
    for (int i = 0; i < RPC; i++) s += vp[(size_t)i * DD];

    __shared__ float cs[64 * 16];
    cs[chunk * 16 + dl] = s;
    __syncthreads();

    float off = 0.f;
    for (int c = 0; c < chunk; c++) off += cs[c * 16 + dl];

    float* op = out + base + (size_t)chunk * RPC * DD + d;
    float acc = off;
#pragma unroll 8
    for (int i = 0; i < RPC; i++) {
        acc += vp[(size_t)i * DD];
        op[(size_t)i * DD] = acc;
    }
}

// ---------------------------------------------------------------------------
// Kernel 2: sparsity metric M[bh, q] = max_s(QK_s) - sum_s(QK_s)/L
// One warp per query. grid = BH*LL/8 blocks of 256 threads (8 warps).
// (round-3 version, unchanged — L2-BW bound, latency hidden by warp count)
// ---------------------------------------------------------------------------
__global__ void m_kernel(const float* __restrict__ Q, const float* __restrict__ K,
                         const int* __restrict__ idxs) {
    const int w    = blockIdx.x * 8 + (threadIdx.x >> 5);
    const int lane = threadIdx.x & 31;
    const int bh   = w >> 11;        // / 2048
    const int q    = w & (LL - 1);
    const size_t base = (size_t)bh * LL * DD;

    const float q0 = __ldg(Q + base + (size_t)q * DD + lane);
    const float q1 = __ldg(Q + base + (size_t)q * DD + 32 + lane);

    float mx = -INFINITY, sm = 0.f;
    const int* ip = idxs + q * SK;
#pragma unroll 4
    for (int s = 0; s < SK; s++) {
        const int idx = __ldg(ip + s);
        const float k0 = __ldg(K + base + (size_t)idx * DD + lane);
        const float k1 = __ldg(K + base + (size_t)idx * DD + 32 + lane);
        float p = q0 * k0 + q1 * k1;
#pragma unroll
        for (int off = 16; off; off >>= 1) p += __shfl_xor_sync(0xffffffffu, p, off);
        mx = fmaxf(mx, p);
        sm += p;
    }
    if (lane == 0) g_M[bh * LL + q] = mx - sm * (1.0f / (float)LL);
}

// ---------------------------------------------------------------------------
// Kernel 3: top-40 of M per (b,h). grid = BH, block = 256 (8 warps).
// ---------------------------------------------------------------------------
__global__ void topk_kernel() {
    const int bh   = blockIdx.x;
    const int t    = threadIdx.x;
    const int warp = t >> 5;
    const int lane = t & 31;

    __shared__ float cv[8][UU];
    __shared__ int   ci[8][UU];

    const int ebase = warp * 256 + lane * 8;
    float v[8];
#pragma unroll
    for (int j = 0; j < 8; j++) v[j] = g_M[bh * LL + ebase + j];

    for (int it = 0; it < UU; it++) {
        float bv = -INFINITY; int bj = 0;
#pragma unroll
        for (int j = 0; j < 8; j++)
            if (v[j] > bv) { bv = v[j]; bj = j; }
        int bidx = ebase + bj;
#pragma unroll
        for (int off = 16; off; off >>= 1) {
            float ov = __shfl_xor_sync(0xffffffffu, bv, off);
            int   oi = __shfl_xor_sync(0xffffffffu, bidx, off);
            if (ov > bv || (ov == bv && oi < bidx)) { bv = ov; bidx = oi; }
        }
        if (bidx >= ebase && bidx < ebase + 8) v[bidx - ebase] = -INFINITY;
        if (lane == 0) { cv[warp][it] = bv; ci[warp][it] = bidx; }
    }
    __syncthreads();

    if (warp == 0) {
        int p = 0;
        for (int it = 0; it < UU; it++) {
            float hv = (lane < 8) ? cv[lane][p] : -INFINITY;
            int   hi = (lane < 8) ? ci[lane][p] : 0x7fffffff;
            float wv = hv; int wi = hi;
#pragma unroll
            for (int off = 4; off; off >>= 1) {
                float ov = __shfl_xor_sync(0xffffffffu, wv, off);
                int   oi = __shfl_xor_sync(0xffffffffu, wi, off);
                if (ov > wv || (ov == wv && oi < wi)) { wv = ov; wi = oi; }
            }
            wv = __shfl_sync(0xffffffffu, wv, 0);
            wi = __shfl_sync(0xffffffffu, wi, 0);
            if (lane < 8 && hi == wi) p++;
            if (lane == 0) g_top[bh * UU + it] = wi;
        }
    }
}

// ---------------------------------------------------------------------------
// Kernel 4: split-K attention partials, warp-autonomous 32-key chunks.
// grid = BH*16, block = 128 (4 warps; warp = one chunk of 32 keys).
// Lane=key for scores (K row in regs), lane=dim for PV (V cols in regs).
// No __syncthreads in the main loop. (round-5 version, proven correct)
// ---------------------------------------------------------------------------
__global__ void __launch_bounds__(128) attn_partial_kernel(const float* __restrict__ Q,
                                                           const float* __restrict__ K,
                                                           const float* __restrict__ V) {
    const int bh   = blockIdx.x >> 4;
    const int cgr  = blockIdx.x & 15;
    const int t    = threadIdx.x;
    const int warp = t >> 5;
    const int lane = t & 31;
    const int c    = cgr * 4 + warp;     // chunk 0..63
    const size_t base = (size_t)bh * LL * DD;
    const int k0 = c * CK;

    __shared__ int   topS[UU];
    __shared__ float Qs[UU][DD];

    if (t < UU) topS[t] = g_top[bh * UU + t];
    __syncthreads();
    for (int i = t; i < UU * 16; i += 128) {
        const int u = i >> 4, j = i & 15;
        *(float4*)&Qs[u][j * 4] = __ldg((const float4*)(Q + base + (size_t)topS[u] * DD) + j);
    }

    // K row of key (k0+lane) -> 64 regs
    float4 kreg[16];
    const float4* kp = (const float4*)(K + base + (size_t)(k0 + lane) * DD);
#pragma unroll
    for (int j = 0; j < 16; j++) kreg[j] = __ldg(kp + j);

    // V columns: lane owns dims (lane) and (lane+32) over 32 keys -> 64 regs
    float v0[CK], v1[CK];
#pragma unroll
    for (int k = 0; k < CK; k++) {
        v0[k] = __ldg(V + base + (size_t)(k0 + k) * DD + lane);
        v1[k] = __ldg(V + base + (size_t)(k0 + k) * DD + 32 + lane);
    }
    __syncthreads();   // Qs ready

    for (int u = 0; u < UU; u++) {
        const int pos = topS[u];
        const int pi  = (bh * UU + u) * NS + c;
        if (k0 > pos) {   // fully masked chunk (warp-uniform)
            if (lane == 0) { g_pm[pi] = -INFINITY; g_pl[pi] = 0.f; }
            continue;
        }
        // score for key k0+lane (Qs reads are warp-broadcast)
        float a0 = 0.f, a1 = 0.f, a2 = 0.f, a3 = 0.f;
#pragma unroll
        for (int j = 0; j < 16; j++) {
            const float4 kv = kreg[j];
            const float4 qv = *(const float4*)&Qs[u][j * 4];
            a0 += kv.x * qv.x; a1 += kv.y * qv.y;
            a2 += kv.z * qv.z; a3 += kv.w * qv.w;
        }
        float s = ((a0 + a1) + (a2 + a3)) * 0.125f;   // 1/sqrt(64)
        const int kg = k0 + lane;
        if (kg > pos) s = -INFINITY;

        float m = s;
#pragma unroll
        for (int off = 16; off; off >>= 1) m = fmaxf(m, __shfl_xor_sync(0xffffffffu, m, off));

        const float p = (kg <= pos) ? __expf(s - m) : 0.f;
        float l = p;
#pragma unroll
        for (int off = 16; off; off >>= 1) l += __shfl_xor_sync(0xffffffffu, l, off);

        // PV: lane = dim; broadcast p_k via shfl
        float acc0 = 0.f, acc1 = 0.f;
#pragma unroll
        for (int k = 0; k < CK; k++) {
            const float pk = __shfl_sync(0xffffffffu, p, k);
            acc0 += pk * v0[k];
            acc1 += pk * v1[k];
        }
        g_pacc[(size_t)pi * DD + lane]      = acc0;
        g_pacc[(size_t)pi * DD + 32 + lane] = acc1;
        if (lane == 0) { g_pm[pi] = m; g_pl[pi] = l; }
    }
}

// ---------------------------------------------------------------------------
// Kernel 5: combine partials (log-sum-exp) and scatter into d_out.
// grid = BH*UU, block = 64 (thread = dim).
// ---------------------------------------------------------------------------
__global__ void combine_kernel(float* __restrict__ out) {
    const int bhu = blockIdx.x;
    const int t   = threadIdx.x;
    const int bh  = bhu / UU;
    const int pos = g_top[bhu];

    float mx = -INFINITY;
#pragma unroll
    for (int c = 0; c < NS; c++) mx = fmaxf(mx, g_pm[bhu * NS + c]);

    float Ls = 0.f, acc = 0.f;
#pragma unroll 8
    for (int c = 0; c < NS; c++) {
        const float plv = g_pl[bhu * NS + c];
        if (plv > 0.f) {
            const float w = __expf(g_pm[bhu * NS + c] - mx);
            Ls  += plv * w;
            acc += w * g_pacc[(size_t)(bhu * NS + c) * DD + t];
        }
    }
    out[(size_t)bh * LL * DD + (size_t)pos * DD + t] = acc / Ls;
}

// ---------------------------------------------------------------------------
extern "C" void kernel_launch(void* const* d_in, const int* in_sizes, int n_in,
                              void* d_out, int out_size) {
    const float* Q   = (const float*)d_in[0];
    const float* K   = (const float*)d_in[1];
    const float* V   = (const float*)d_in[2];
    const int*   idx = (const int*)d_in[3];
    float* out = (float*)d_out;

    cumsum_kernel<<<BH * 4, 1024>>>(V, out);
    m_kernel<<<BH * LL / 8, 256>>>(Q, K, idx);
    topk_kernel<<<BH, 256>>>();
    attn_partial_kernel<<<BH * 16, 128>>>(Q, K, V);
    combine_kernel<<<BH * UU, DD>>>(out);
}

// round 7
// speedup vs baseline: 1.3679x; 1.2487x over previous
#include <cuda_runtime.h>
#include <math.h>

// Fixed problem shapes
#define BH 32            // B*H
#define LL 2048
#define DD 64
#define UU 40            // top-k count
#define SK 40            // sample_k
#define NS 64            // key-chunks for split softmax (warp-sized chunks)
#define CK 32            // keys per chunk (NS*CK == LL)

// Scratch (device globals; no allocation allowed)
__device__ float g_M[BH * LL];
__device__ int   g_top[BH * UU];
__device__ float g_pm[BH * UU * NS];
__device__ float g_pl[BH * UU * NS];
__device__ float g_pacc[BH * UU * NS * DD];   // 21 MB
__device__ float g_cv[BH * 8 * UU];           // per-segment sorted top-40 values
__device__ int   g_ci[BH * 8 * UU];           // per-segment sorted top-40 indices

// ---------------------------------------------------------------------------
// Kernel 1: cumsum of values along L, written to d_out.
// grid = BH*4 (16-dim groups), block = 1024.
// ---------------------------------------------------------------------------
__global__ void cumsum_kernel(const float* __restrict__ V, float* __restrict__ out) {
    const int bh    = blockIdx.x >> 2;
    const int dg    = blockIdx.x & 3;
    const int dl    = threadIdx.x & 15;
    const int d     = dg * 16 + dl;
    const int chunk = threadIdx.x >> 4;     // 0..63
    const int RPC   = 32;
    const size_t base = (size_t)bh * LL * DD;
    const float* vp = V + base + (size_t)chunk * RPC * DD + d;

    float s = 0.f;
#pragma unroll 8
    for (int i = 0; i < RPC; i++) s += vp[(size_t)i * DD];

    __shared__ float cs[64 * 16];
    cs[chunk * 16 + dl] = s;
    __syncthreads();

    float off = 0.f;
    for (int c = 0; c < chunk; c++) off += cs[c * 16 + dl];

    float* op = out + base + (size_t)chunk * RPC * DD + d;
    float acc = off;
#pragma unroll 8
    for (int i = 0; i < RPC; i++) {
        acc += vp[(size_t)i * DD];
        op[(size_t)i * DD] = acc;
    }
}

// ---------------------------------------------------------------------------
// Kernel 2: M[bh,q] = max_s(QK_s) - sum_s(QK_s)/L.
// Warp per query; 4 samples per iteration across 8-lane groups (0.75 shfl per
// sample vs 5). Dot ordering identical to the round-5-validated m3 kernel.
// grid = BH*LL/8 blocks of 256 threads.
// ---------------------------------------------------------------------------
__global__ void m_kernel(const float* __restrict__ Q, const float* __restrict__ K,
                         const int* __restrict__ idxs) {
    const int w    = blockIdx.x * 8 + (threadIdx.x >> 5);
    const int lane = threadIdx.x & 31;
    const int bh   = w >> 11;        // / 2048
    const int q    = w & (LL - 1);
    const size_t base = (size_t)bh * LL * DD;
    const int g     = lane & 7;      // dim-group within sample (8 dims x [lo,hi])
    const int s_sub = lane >> 3;     // which of 4 samples this iteration

    // Q dims [4g,4g+4) and [32+4g, 32+4g+4)
    const float4 qa  = __ldg((const float4*)(Q + base + (size_t)q * DD) + g);
    const float4 qb4 = __ldg((const float4*)(Q + base + (size_t)q * DD) + 8 + g);

    const int* ip = idxs + q * SK;
    float lm = -INFINITY, ls = 0.f;
#pragma unroll
    for (int bb = 0; bb < SK; bb += 4) {          // 10 iterations
        const int sidx = __ldg(ip + bb + s_sub);  // 4 consecutive ints / warp
        const float4 ka = __ldg((const float4*)(K + base + (size_t)sidx * DD) + g);
        const float4 kb = __ldg((const float4*)(K + base + (size_t)sidx * DD) + 8 + g);
        float d = qa.x * ka.x + qa.y * ka.y + qa.z * ka.z + qa.w * ka.w
                + qb4.x * kb.x + qb4.y * kb.y + qb4.z * kb.z + qb4.w * kb.w;
        d += __shfl_xor_sync(0xffffffffu, d, 1);
        d += __shfl_xor_sync(0xffffffffu, d, 2);
        d += __shfl_xor_sync(0xffffffffu, d, 4);
        lm = fmaxf(lm, d);
        ls += d;
    }
    // combine the 4 sample-groups
    lm = fmaxf(lm, __shfl_xor_sync(0xffffffffu, lm, 8));
    ls += __shfl_xor_sync(0xffffffffu, ls, 8);
    lm = fmaxf(lm, __shfl_xor_sync(0xffffffffu, lm, 16));
    ls += __shfl_xor_sync(0xffffffffu, ls, 16);
    if (lane == 0) g_M[bh * LL + q] = lm - ls * (1.0f / (float)LL);
}

// ---------------------------------------------------------------------------
// Kernel 3a: per-segment sorted top-40. grid = BH*8, block = 32 (1 warp).
// ---------------------------------------------------------------------------
__global__ void topk_local_kernel() {
    const int blk  = blockIdx.x;          // bh*8 + seg
    const int bh   = blk >> 3;
    const int seg  = blk & 7;
    const int lane = threadIdx.x;
    const int ebase = seg * 256 + lane * 8;

    float v[8];
#pragma unroll
    for (int j = 0; j < 8; j++) v[j] = g_M[bh * LL + ebase + j];

    for (int it = 0; it < UU; it++) {
        float bv = -INFINITY; int bj = 0;
#pragma unroll
        for (int j = 0; j < 8; j++)
            if (v[j] > bv) { bv = v[j]; bj = j; }
        int bidx = ebase + bj;
#pragma unroll
        for (int off = 16; off; off >>= 1) {
            float ov = __shfl_xor_sync(0xffffffffu, bv, off);
            int   oi = __shfl_xor_sync(0xffffffffu, bidx, off);
            if (ov > bv || (ov == bv && oi < bidx)) { bv = ov; bidx = oi; }
        }
        if (bidx >= ebase && bidx < ebase + 8) v[bidx - ebase] = -INFINITY;
        if (lane == 0) { g_cv[blk * UU + it] = bv; g_ci[blk * UU + it] = bidx; }
    }
}

// ---------------------------------------------------------------------------
// Kernel 3b: 8-way merge of sorted lists. grid = BH, block = 32.
// ---------------------------------------------------------------------------
__global__ void topk_merge_kernel() {
    const int bh   = blockIdx.x;
    const int lane = threadIdx.x;

    __shared__ float sv[8][UU];
    __shared__ int   si[8][UU];
    // stage 8*40 entries into smem (10 per lane)
    for (int i = lane; i < 8 * UU; i += 32) {
        sv[i / UU][i % UU] = g_cv[bh * 8 * UU + i];
        si[i / UU][i % UU] = g_ci[bh * 8 * UU + i];
    }
    __syncwarp();

    int p = 0;   // head pointer for list `lane` (lanes 0..7)
    for (int it = 0; it < UU; it++) {
        float hv = (lane < 8) ? sv[lane][p] : -INFINITY;
        int   hi = (lane < 8) ? si[lane][p] : 0x7fffffff;
        float wv = hv; int wi = hi;
#pragma unroll
        for (int off = 4; off; off >>= 1) {
            float ov = __shfl_xor_sync(0xffffffffu, wv, off);
            int   oi = __shfl_xor_sync(0xffffffffu, wi, off);
            if (ov > wv || (ov == wv && oi < wi)) { wv = ov; wi = oi; }
        }
        wv = __shfl_sync(0xffffffffu, wv, 0);
        wi = __shfl_sync(0xffffffffu, wi, 0);
        if (lane < 8 && hi == wi) p++;
        if (lane == 0) g_top[bh * UU + it] = wi;
    }
}

// ---------------------------------------------------------------------------
// Kernel 4: split-K attention partials, warp-autonomous 32-key chunks.
// grid = BH*16, block = 128. Balanced chunk map: c = ((warp+cgr)&3)*16 + cgr
// so each block holds one chunk per quadrant and heavy quadrants rotate
// across warp slots (SMSPs).
// ---------------------------------------------------------------------------
__global__ void __launch_bounds__(128) attn_partial_kernel(const float* __restrict__ Q,
                                                           const float* __restrict__ K,
                                                           const float* __restrict__ V) {
    const int bh   = blockIdx.x >> 4;
    const int cgr  = blockIdx.x & 15;
    const int t    = threadIdx.x;
    const int warp = t >> 5;
    const int lane = t & 31;
    const int c    = (((warp + cgr) & 3) << 4) + cgr;   // chunk 0..63
    const size_t base = (size_t)bh * LL * DD;
    const int k0 = c * CK;

    __shared__ int   topS[UU];
    __shared__ float Qs[UU][DD];

    if (t < UU) topS[t] = g_top[bh * UU + t];
    __syncthreads();
    for (int i = t; i < UU * 16; i += 128) {
        const int u = i >> 4, j = i & 15;
        *(float4*)&Qs[u][j * 4] = __ldg((const float4*)(Q + base + (size_t)topS[u] * DD) + j);
    }

    // K row of key (k0+lane) -> 64 regs
    float4 kreg[16];
    const float4* kp = (const float4*)(K + base + (size_t)(k0 + lane) * DD);
#pragma unroll
    for (int j = 0; j < 16; j++) kreg[j] = __ldg(kp + j);

    // V columns: lane owns dims (lane) and (lane+32) over 32 keys -> 64 regs
    float v0[CK], v1[CK];
#pragma unroll
    for (int k = 0; k < CK; k++) {
        v0[k] = __ldg(V + base + (size_t)(k0 + k) * DD + lane);
        v1[k] = __ldg(V + base + (size_t)(k0 + k) * DD + 32 + lane);
    }
    __syncthreads();   // Qs ready

    for (int u = 0; u < UU; u++) {
        const int pos = topS[u];
        const int pi  = (bh * UU + u) * NS + c;
        if (k0 > pos) {   // fully masked chunk (warp-uniform)
            if (lane == 0) { g_pm[pi] = -INFINITY; g_pl[pi] = 0.f; }
            continue;
        }
        // score for key k0+lane (Qs reads are warp-broadcast)
        float a0 = 0.f, a1 = 0.f, a2 = 0.f, a3 = 0.f;
#pragma unroll
        for (int j = 0; j < 16; j++) {
            const float4 kv = kreg[j];
            const float4 qv = *(const float4*)&Qs[u][j * 4];
            a0 += kv.x * qv.x; a1 += kv.y * qv.y;
            a2 += kv.z * qv.z; a3 += kv.w * qv.w;
        }
        float s = ((a0 + a1) + (a2 + a3)) * 0.125f;   // 1/sqrt(64)
        const int kg = k0 + lane;
        if (kg > pos) s = -INFINITY;

        float m = s;
#pragma unroll
        for (int off = 16; off; off >>= 1) m = fmaxf(m, __shfl_xor_sync(0xffffffffu, m, off));

        const float p = (kg <= pos) ? __expf(s - m) : 0.f;
        float l = p;
#pragma unroll
        for (int off = 16; off; off >>= 1) l += __shfl_xor_sync(0xffffffffu, l, off);

        // PV: lane = dim; broadcast p_k via shfl
        float acc0 = 0.f, acc1 = 0.f;
#pragma unroll
        for (int k = 0; k < CK; k++) {
            const float pk = __shfl_sync(0xffffffffu, p, k);
            acc0 += pk * v0[k];
            acc1 += pk * v1[k];
        }
        g_pacc[(size_t)pi * DD + lane]      = acc0;
        g_pacc[(size_t)pi * DD + 32 + lane] = acc1;
        if (lane == 0) { g_pm[pi] = m; g_pl[pi] = l; }
    }
}

// ---------------------------------------------------------------------------
// Kernel 5: combine partials (log-sum-exp) and scatter into d_out.
// grid = BH*UU, block = 64 (thread = dim).
// ---------------------------------------------------------------------------
__global__ void combine_kernel(float* __restrict__ out) {
    const int bhu = blockIdx.x;
    const int t   = threadIdx.x;
    const int bh  = bhu / UU;
    const int pos = g_top[bhu];

    float mx = -INFINITY;
#pragma unroll
    for (int c = 0; c < NS; c++) mx = fmaxf(mx, g_pm[bhu * NS + c]);

    float Ls = 0.f, acc = 0.f;
#pragma unroll 8
    for (int c = 0; c < NS; c++) {
        const float plv = g_pl[bhu * NS + c];
        if (plv > 0.f) {
            const float w = __expf(g_pm[bhu * NS + c] - mx);
            Ls  += plv * w;
            acc += w * g_pacc[(size_t)(bhu * NS + c) * DD + t];
        }
    }
    out[(size_t)bh * LL * DD + (size_t)pos * DD + t] = acc / Ls;
}

// ---------------------------------------------------------------------------
extern "C" void kernel_launch(void* const* d_in, const int* in_sizes, int n_in,
                              void* d_out, int out_size) {
    const float* Q   = (const float*)d_in[0];
    const float* K   = (const float*)d_in[1];
    const float* V   = (const float*)d_in[2];
    const int*   idx = (const int*)d_in[3];
    float* out = (float*)d_out;

    cumsum_kernel<<<BH * 4, 1024>>>(V, out);
    m_kernel<<<BH * LL / 8, 256>>>(Q, K, idx);
    topk_local_kernel<<<BH * 8, 32>>>();
    topk_merge_kernel<<<BH, 32>>>();
    attn_partial_kernel<<<BH * 16, 128>>>(Q, K, V);
    combine_kernel<<<BH * UU, DD>>>(out);
}